// round 5
// baseline (speedup 1.0000x reference)
#include <cuda_runtime.h>
#include <math.h>

#define NN 4096
#define FF 256
#define EE 65536
#define MAXD 96      // max 1-hop degree incl diag (Poisson(16) tail; huge margin)
#define MAXR 2048    // max 2-hop neighborhood size (observed ~300-700)

// ---------------- device scratch (allocation-free rule: __device__ globals) ----
__device__ float g_A [(size_t)NN * NN];   // dense A (then left intact)
__device__ float g_A2[(size_t)NN * NN];   // dense A2, overwritten in-place with adj_k
__device__ int   g_nbrCnt[NN];
__device__ int   g_nbrCol[NN * MAXD];
__device__ float g_nbrVal[NN * MAXD];
__device__ int   g_D[NN];
__device__ float g_sq[NN];
__device__ unsigned long long g_S1;       // sum D   (integer -> order-independent)
__device__ unsigned long long g_S2;       // sum D^2

// ---------------- kernels -----------------------------------------------------

__global__ void k_zero()
{
    size_t n4 = (size_t)NN * NN / 4;
    float4 z = make_float4(0.f, 0.f, 0.f, 0.f);
    float4* p = reinterpret_cast<float4*>(g_A);
    for (size_t i = blockIdx.x * (size_t)blockDim.x + threadIdx.x; i < n4;
         i += (size_t)gridDim.x * blockDim.x)
        p[i] = z;
    if (blockIdx.x == 0 && threadIdx.x == 0) { g_S1 = 0ull; g_S2 = 0ull; }
}

__global__ void k_scatter(const int* __restrict__ ei, const float* __restrict__ w)
{
    int i = blockIdx.x * blockDim.x + threadIdx.x;
    if (i < EE) {
        int u = ei[i];
        int v = ei[EE + i];
        atomicAdd(&g_A[(size_t)u * NN + v], w[i]);
    }
}

// A = A + I; clamp(>1 -> 1)
__global__ void k_finalize()
{
    size_t i = blockIdx.x * (size_t)blockDim.x + threadIdx.x;
    if (i < (size_t)NN * NN) {
        int r = (int)(i >> 12);
        int c = (int)(i & (NN - 1));
        float v = g_A[i];
        if (r == c) v += 1.f;
        if (v > 1.f) v = 1.f;
        g_A[i] = v;
    }
}

// warp-per-row: compact nonzeros of A (incl diag, col-ascending = deterministic),
// D[u] = cnt-1, integer degree-stat atomics.
__global__ void k_nbr()
{
    int w    = (blockIdx.x * blockDim.x + threadIdx.x) >> 5;
    int lane = threadIdx.x & 31;
    if (w >= NN) return;
    const float* row = g_A + (size_t)w * NN;
    int cnt = 0;
    for (int c0 = 0; c0 < NN; c0 += 32) {
        float v = row[c0 + lane];
        unsigned m = __ballot_sync(0xffffffffu, v != 0.f);
        if (v != 0.f) {
            int p = cnt + __popc(m & ((1u << lane) - 1u));
            if (p < MAXD) {
                g_nbrCol[w * MAXD + p] = c0 + lane;
                g_nbrVal[w * MAXD + p] = v;
            }
        }
        cnt += __popc(m);
    }
    if (cnt > MAXD) cnt = MAXD;
    if (lane == 0) {
        g_nbrCnt[w] = cnt;
        int D = cnt - 1;                 // diag (==1) always present
        g_D[w] = D;
        atomicAdd(&g_S1, (unsigned long long)D);
        atomicAdd(&g_S2, (unsigned long long)((long long)D * D));
    }
}

// warp-per-node squared norms (fixed reduction order)
__global__ void k_sq(const float* __restrict__ X)
{
    int w    = (blockIdx.x * blockDim.x + threadIdx.x) >> 5;
    int lane = threadIdx.x & 31;
    if (w >= NN) return;
    const float* x = X + (size_t)w * FF;
    float s = 0.f;
#pragma unroll
    for (int k = 0; k < FF / 32; k++) { float a = x[lane + 32 * k]; s += a * a; }
#pragma unroll
    for (int o = 16; o; o >>= 1) s += __shfl_xor_sync(0xffffffffu, s, o);
    if (lane == 0) g_sq[w] = s;
}

// SpGEMM: block-per-row, smem dense-row accumulator.
// Deterministic: sequential over k, parallel over disjoint cols within each k.
__global__ void k_spgemm()
{
    __shared__ float acc[NN];            // 16 KB
    int u = blockIdx.x;
    for (int i = threadIdx.x; i < NN; i += blockDim.x) acc[i] = 0.f;
    __syncthreads();
    int cnt = g_nbrCnt[u];
    for (int t = 0; t < cnt; t++) {
        int   k = g_nbrCol[u * MAXD + t];
        float a = g_nbrVal[u * MAXD + t];
        int  ck = g_nbrCnt[k];
        if ((int)threadIdx.x < ck)
            acc[g_nbrCol[k * MAXD + threadIdx.x]] += a * g_nbrVal[k * MAXD + threadIdx.x];
        __syncthreads();
    }
    float* out = g_A2 + (size_t)u * NN;
    for (int i = threadIdx.x; i < NN; i += blockDim.x) out[i] = acc[i];
}

// Main per-row kernel: branch per node, rewrite g_A2 row in-place as adj_k.
__global__ void k_main(const float* __restrict__ X)
{
    __shared__ int   scol [MAXR];
    __shared__ float sa2  [MAXR];
    __shared__ float sdist[MAXR];
    __shared__ float xu[FF];
    __shared__ int   cntS;

    int u   = blockIdx.x;
    int tid = threadIdx.x;
    const float* a2row = g_A2 + (size_t)u * NN;
    const float* arow  = g_A  + (size_t)u * NN;

    if (tid == 0) cntS = 0;
    __syncthreads();

    // compact off-diag nonzeros of A2 row (order-irrelevant downstream)
    for (int c = tid; c < NN; c += blockDim.x) {
        float v = a2row[c];
        if (v != 0.f && c != u) {
            int p = atomicAdd(&cntS, 1);
            if (p < MAXR) { scol[p] = c; sa2[p] = v; }
        }
    }
    __syncthreads();

    int Dr = cntS; if (Dr > MAXR) Dr = MAXR;
    int D  = g_D[u];

    // d_thres = mean(D) + 2*std(D)  (population), from exact integer sums
    double S1 = (double)g_S1, S2 = (double)g_S2;
    double mean = S1 / (double)NN;
    double var  = S2 / (double)NN - mean * mean;
    if (var < 0.0) var = 0.0;
    double dth  = mean + 2.0 * sqrt(var);
    bool highD  = ((double)D > dth);
    int  nz     = Dr - 2 * D;

    if (highD) {
        // Z = (A == 0): keep A2-A only where 1-hop edge exists
        for (int i = tid; i < Dr; i += blockDim.x) {
            int c = scol[i];
            float a = arow[c];
            g_A2[(size_t)u * NN + c] = (a != 0.f) ? (sa2[i] - a) : 0.f;
        }
    } else if (nz < 0) {
        // no-sparse branch: adj_k = A2 - A everywhere
        for (int i = tid; i < Dr; i += blockDim.x) {
            int c = scol[i];
            g_A2[(size_t)u * NN + c] = sa2[i] - arow[c];
        }
    } else if (nz == 0) {
        // nz_eff = n -> all neighbors selected -> entire row zero
        for (int i = tid; i < Dr; i += blockDim.x)
            g_A2[(size_t)u * NN + scol[i]] = 0.f;
    } else {
        // sparse branch: zero the nz farthest (stable-tie) neighbors
        for (int f = tid; f < FF; f += blockDim.x) xu[f] = X[(size_t)u * FF + f];
        __syncthreads();
        float squ = g_sq[u];

        // warp-per-neighbor dot products (coalesced X_v reads, fixed reduce order)
        int warp = tid >> 5, lane = tid & 31;
        for (int i = warp; i < Dr; i += (int)(blockDim.x >> 5)) {
            int v = scol[i];
            const float* xv = X + (size_t)v * FF;
            float s = 0.f;
#pragma unroll 4
            for (int f = lane; f < FF; f += 32) s += xu[f] * xv[f];
#pragma unroll
            for (int o = 16; o; o >>= 1) s += __shfl_xor_sync(0xffffffffu, s, o);
            if (lane == 0) sdist[i] = squ + g_sq[v] - 2.f * s;
        }
        __syncthreads();

        // rank(v) = #{d_j > d_v} + #{d_j == d_v, col_j < col_v}   (stable argsort)
        for (int i = tid; i < Dr; i += blockDim.x) {
            float di = sdist[i];
            int   ci = scol[i];
            int r = 0;
            for (int j = 0; j < Dr; j++) {
                float dj = sdist[j];
                r += (dj > di) || (dj == di && scol[j] < ci);
            }
            float out = (r < nz) ? 0.f : (sa2[i] - arow[ci]);
            g_A2[(size_t)u * NN + ci] = out;
        }
    }
    if (tid == 0) g_A2[(size_t)u * NN + u] = 0.f;   // diag always zero
}

__global__ void k_edge(const int* __restrict__ ei, const float* __restrict__ w,
                       const float* __restrict__ t1, const float* __restrict__ t2,
                       float* __restrict__ out)
{
    int i = blockIdx.x * blockDim.x + threadIdx.x;
    if (i < EE) {
        int u = ei[i];
        int v = ei[EE + i];
        float val = t1[0] * w[i] + t2[0] * g_A2[(size_t)u * NN + v];
        out[i] = fmaxf(val, 0.f);
    }
}

// ---------------- launch ------------------------------------------------------

extern "C" void kernel_launch(void* const* d_in, const int* in_sizes, int n_in,
                              void* d_out, int out_size)
{
    (void)in_sizes; (void)n_in; (void)out_size;
    const int*   edge_index = (const int*)  d_in[0];   // (2, E) int32
    const float* edge_w     = (const float*)d_in[1];   // (E,)
    const float* features   = (const float*)d_in[2];   // (N, F)
    const float* theta_1    = (const float*)d_in[3];   // (1,)
    const float* theta_2    = (const float*)d_in[4];   // (1,)
    float*       out        = (float*)      d_out;     // (E,)

    k_zero    <<<2048, 256>>>();
    k_scatter <<<EE / 256, 256>>>(edge_index, edge_w);
    k_finalize<<<(int)(((size_t)NN * NN + 255) / 256), 256>>>();
    k_nbr     <<<NN / 8, 256>>>();
    k_sq      <<<NN / 8, 256>>>(features);
    k_spgemm  <<<NN, 128>>>();
    k_main    <<<NN, 256>>>(features);
    k_edge    <<<EE / 256, 256>>>(edge_index, edge_w, theta_1, theta_2, out);
}

// round 6
// speedup vs baseline: 1.6099x; 1.6099x over previous
#include <cuda_runtime.h>
#include <math.h>

#define NN 4096
#define FF 256
#define EE 65536
#define MAXD 96      // max 1-hop degree incl diag (Poisson(16); huge margin)
#define MAXR 2048    // max 2-hop neighborhood size (observed ~300-700)

// ---------------- device scratch (allocation-free rule: __device__ globals) ----
// g_A: transient scatter buffer. Zero-initialized at module load; every launch
//      returns it to all-zeros via the atomicExch dedup pass (self-cleaning).
__device__ float g_A [(size_t)NN * NN];
// g_A2: sparse adj_k store. Written only at A2-nonzero off-diag positions with
//      replay-identical values; untouched cells stay 0 from static init.
__device__ float g_A2[(size_t)NN * NN];
__device__ int   g_nbrCnt[NN];
__device__ int   g_nbrCol[NN * MAXD];
__device__ float g_nbrVal[NN * MAXD];
__device__ int   g_D[NN];
__device__ float g_sq[NN];
__device__ unsigned long long g_S1;   // sum D   (integer -> exact, order-free)
__device__ unsigned long long g_S2;   // sum D^2

// ---------------- kernels -----------------------------------------------------

// scatter edge weights; also reset per-launch counters (used only by later kernels)
__global__ void k_scatter(const int* __restrict__ ei, const float* __restrict__ w)
{
    int i = blockIdx.x * blockDim.x + threadIdx.x;
    if (i < NN) g_nbrCnt[i] = 0;
    if (i == 0) { g_S1 = 0ull; g_S2 = 0ull; }
    if (i < EE) {
        int u = ei[i];
        int v = ei[EE + i];
        atomicAdd(&g_A[(size_t)u * NN + v], w[i]);
    }
}

// dedup via atomicExch: winner gets the summed weight, cell is restored to 0.
// Builds compact per-row neighbor lists (clamped values). Self-loops are
// claimed+cleaned but not appended (diag handled separately, value == 1).
__global__ void k_build(const int* __restrict__ ei)
{
    int i = blockIdx.x * blockDim.x + threadIdx.x;
    if (i >= EE) return;
    int u = ei[i];
    int v = ei[EE + i];
    float val = atomicExch(&g_A[(size_t)u * NN + v], 0.f);
    if (val != 0.f && u != v) {
        int p = atomicAdd(&g_nbrCnt[u], 1);
        if (p < MAXD - 1) {
            g_nbrCol[u * MAXD + p] = v;
            g_nbrVal[u * MAXD + p] = fminf(val, 1.f);   // clamp A>1 -> 1
        }
    }
}

// append diag (==1 exactly: clamp(raw+1)->1, or 1 when raw==0), finalize D,
// accumulate integer degree stats.
__global__ void k_diag()
{
    int u = blockIdx.x * blockDim.x + threadIdx.x;
    if (u >= NN) return;
    int c = g_nbrCnt[u]; if (c > MAXD - 1) c = MAXD - 1;
    g_nbrCol[u * MAXD + c] = u;
    g_nbrVal[u * MAXD + c] = 1.f;
    g_nbrCnt[u] = c + 1;
    g_D[u] = c;                                  // off-diag nonzero count
    atomicAdd(&g_S1, (unsigned long long)c);
    atomicAdd(&g_S2, (unsigned long long)((long long)c * c));
}

// warp-per-node squared norms (fixed reduction order)
__global__ void k_sq(const float* __restrict__ X)
{
    int w    = (blockIdx.x * blockDim.x + threadIdx.x) >> 5;
    int lane = threadIdx.x & 31;
    if (w >= NN) return;
    const float* x = X + (size_t)w * FF;
    float s = 0.f;
#pragma unroll
    for (int k = 0; k < FF / 32; k++) { float a = x[lane + 32 * k]; s += a * a; }
#pragma unroll
    for (int o = 16; o; o >>= 1) s += __shfl_xor_sync(0xffffffffu, s, o);
    if (lane == 0) g_sq[w] = s;
}

// Fused per-row kernel: SpGEMM row in smem -> compact -> branch -> sparse write.
__global__ void k_main(const float* __restrict__ X)
{
    __shared__ float acc  [NN];     // 16 KB  A2 row accumulator (also sa2 source)
    __shared__ int   scol [MAXR];   //  8 KB
    __shared__ float sdist[MAXR];   //  8 KB
    __shared__ float xu   [FF];     //  1 KB
    __shared__ int   ucol [MAXD];
    __shared__ float uval [MAXD];
    __shared__ int   cntS;

    int u   = blockIdx.x;
    int tid = threadIdx.x;

    for (int i = tid; i < NN; i += blockDim.x) acc[i] = 0.f;
    int cnt = g_nbrCnt[u];
    if (tid < cnt) { ucol[tid] = g_nbrCol[u * MAXD + tid];
                     uval[tid] = g_nbrVal[u * MAXD + tid]; }
    if (tid == 0) cntS = 0;
    __syncthreads();

    // SpGEMM: sequential over k (replay-consistent per launch), parallel over
    // the disjoint columns of row k.
    for (int t = 0; t < cnt; t++) {
        int   k = ucol[t];
        float a = uval[t];
        int  ck = g_nbrCnt[k];
        if (tid < ck)
            acc[g_nbrCol[k * MAXD + tid]] += a * g_nbrVal[k * MAXD + tid];
        __syncthreads();
    }

    // compact off-diag nonzeros (order irrelevant: all downstream is set-based)
    for (int c = tid; c < NN; c += blockDim.x) {
        float v = acc[c];
        if (v != 0.f && c != u) {
            int p = atomicAdd(&cntS, 1);
            if (p < MAXR) scol[p] = c;
        }
    }
    __syncthreads();

    int Dr = cntS; if (Dr > MAXR) Dr = MAXR;
    int D  = g_D[u];

    // d_thres = mean(D) + 2*std(D) from exact integer sums
    double S1 = (double)g_S1, S2 = (double)g_S2;
    double mean = S1 / (double)NN;
    double var  = S2 / (double)NN - mean * mean;
    if (var < 0.0) var = 0.0;
    double dth  = mean + 2.0 * sqrt(var);
    bool highD  = ((double)D > dth);
    int  nz     = Dr - 2 * D;

    float* outrow = g_A2 + (size_t)u * NN;

    if (highD) {
        // Z = (A == 0): keep A2-A only at 1-hop edges (A!=0 => A2!=0, covered)
        for (int i = tid; i < Dr; i += blockDim.x) {
            int c = scol[i];
            float a = 0.f;
            for (int j = 0; j < cnt; j++) if (ucol[j] == c) { a = uval[j]; break; }
            outrow[c] = (a != 0.f) ? (acc[c] - a) : 0.f;
        }
    } else if (nz < 0) {
        // no-sparse branch: adj_k = A2 - A everywhere
        for (int i = tid; i < Dr; i += blockDim.x) {
            int c = scol[i];
            float a = 0.f;
            for (int j = 0; j < cnt; j++) if (ucol[j] == c) { a = uval[j]; break; }
            outrow[c] = acc[c] - a;
        }
    } else if (nz == 0) {
        // nz_eff = n -> all neighbors selected -> entire row zero
        for (int i = tid; i < Dr; i += blockDim.x) outrow[scol[i]] = 0.f;
    } else {
        // sparse branch: zero the nz farthest (stable-tie) neighbors
        for (int f = tid; f < FF; f += blockDim.x) xu[f] = X[(size_t)u * FF + f];
        __syncthreads();
        float squ = g_sq[u];

        // warp-per-neighbor dot products: dual float4 loads for MLP,
        // fixed reduction order.
        int warp = tid >> 5, lane = tid & 31;
        const float4* xu4 = reinterpret_cast<const float4*>(xu);
        for (int i = warp; i < Dr; i += (int)(blockDim.x >> 5)) {
            int v = scol[i];
            const float4* xv4 = reinterpret_cast<const float4*>(X + (size_t)v * FF);
            float4 a0 = xv4[lane], a1 = xv4[lane + 32];
            float4 b0 = xu4[lane], b1 = xu4[lane + 32];
            float s = a0.x * b0.x;
            s += a0.y * b0.y;  s += a0.z * b0.z;  s += a0.w * b0.w;
            s += a1.x * b1.x;  s += a1.y * b1.y;
            s += a1.z * b1.z;  s += a1.w * b1.w;
#pragma unroll
            for (int o = 16; o; o >>= 1) s += __shfl_xor_sync(0xffffffffu, s, o);
            if (lane == 0) sdist[i] = squ + g_sq[v] - 2.f * s;
        }
        __syncthreads();

        // rank(v) = #{d_j > d_v} + #{d_j == d_v, col_j < col_v} (stable argsort)
        for (int i = tid; i < Dr; i += blockDim.x) {
            float di = sdist[i];
            int   ci = scol[i];
            int r = 0;
            for (int j = 0; j < Dr; j++) {
                float dj = sdist[j];
                r += (dj > di) || (dj == di && scol[j] < ci);
            }
            float out;
            if (r < nz) out = 0.f;
            else {
                float a = 0.f;
                for (int j = 0; j < cnt; j++) if (ucol[j] == ci) { a = uval[j]; break; }
                out = acc[ci] - a;
            }
            outrow[ci] = out;
        }
    }
    // diag of adj_k is 0: never written -> stays 0 from static init
}

__global__ void k_edge(const int* __restrict__ ei, const float* __restrict__ w,
                       const float* __restrict__ t1, const float* __restrict__ t2,
                       float* __restrict__ out)
{
    int i = blockIdx.x * blockDim.x + threadIdx.x;
    if (i < EE) {
        int u = ei[i];
        int v = ei[EE + i];
        float val = t1[0] * w[i] + t2[0] * g_A2[(size_t)u * NN + v];
        out[i] = fmaxf(val, 0.f);
    }
}

// ---------------- launch ------------------------------------------------------

extern "C" void kernel_launch(void* const* d_in, const int* in_sizes, int n_in,
                              void* d_out, int out_size)
{
    (void)in_sizes; (void)n_in; (void)out_size;
    const int*   edge_index = (const int*)  d_in[0];   // (2, E) int32
    const float* edge_w     = (const float*)d_in[1];   // (E,)
    const float* features   = (const float*)d_in[2];   // (N, F)
    const float* theta_1    = (const float*)d_in[3];   // (1,)
    const float* theta_2    = (const float*)d_in[4];   // (1,)
    float*       out        = (float*)      d_out;     // (E,)

    k_scatter<<<EE / 256, 256>>>(edge_index, edge_w);
    k_build  <<<EE / 256, 256>>>(edge_index);
    k_diag   <<<NN / 256, 256>>>();
    k_sq     <<<NN / 8,   256>>>(features);
    k_main   <<<NN,       256>>>(features);
    k_edge   <<<EE / 256, 256>>>(edge_index, edge_w, theta_1, theta_2, out);
}